// round 7
// baseline (speedup 1.0000x reference)
#include <cuda_runtime.h>
#include <cuda_fp16.h>

#define NN 50000
#define NE 800000
#define NTOT (NE + NN)
#define NF 128
#define NH 256
#define NC 40
#define KHOPS 10

// ---------------- device scratch (static, no runtime alloc) ----------------
__device__ int   g_mode;           // 1 = edge_index is int64, 0 = int32
__device__ int   g_esrc[NE];
__device__ int   g_edst[NE];
__device__ __align__(16) int g_cnt[NN + 64];
__device__ int   g_ptr[NN + 1];
__device__ float g_dinv[NN];
__device__ int   g_src[NTOT];
__device__ __align__(16) float  g_w[NTOT];
__device__ __align__(16) __half g_h0[NN * NF];
__device__ __align__(16) __half g_h1[NN * NF];
__device__ __align__(16) float  g_hidden[NN * NF];
__device__ __align__(16) float  g_z1[(size_t)NN * NH];

// ---------------- launch 1: init cnt + dtype detect ----------------
__global__ void k_pre(const void* __restrict__ ei) {
    int i = blockIdx.x * blockDim.x + threadIdx.x;
    if (i < NN) g_cnt[i] = 1;  // self loop
    if (blockIdx.x == 0 && threadIdx.x < 32) {
        const long long* p = (const long long*)ei;
        int t = threadIdx.x;
        int bad = 0;
#pragma unroll
        for (int j = 0; j < 8; j++) {
            long long v = p[t + j * 32];
            if (v < 0 || v >= NN) bad = 1;
        }
        unsigned m = __ballot_sync(0xFFFFFFFFu, bad);
        if (t == 0) g_mode = (m == 0) ? 1 : 0;
    }
}

// ---------------- launch 2: convert edges + count degrees ----------------
__global__ void k_convert(const void* __restrict__ ei) {
    int i = blockIdx.x * blockDim.x + threadIdx.x;
    if (i >= NE) return;
    int s, d;
    if (g_mode) {
        const long long* p = (const long long*)ei;
        s = (int)p[i];
        d = (int)p[NE + i];
    } else {
        const int* p = (const int*)ei;
        s = p[i];
        d = p[NE + i];
    }
    g_esrc[i] = s;
    g_edst[i] = d;
    if ((unsigned)d < NN) atomicAdd(&g_cnt[d], 1);
}

// ---------------- launch 3: single-block scan + dinv + zero cnt ----------
__global__ void k_scan() {
    __shared__ int wsum[32];
    __shared__ int s_tot;
    int tid = threadIdx.x, lane = tid & 31, w = tid >> 5;
    int carry = 0;
    const int ITERS = (NN + 4095) / 4096;  // 13
    for (int it = 0; it < ITERS; it++) {
        int base = it * 4096 + tid * 4;
        int c0 = 0, c1 = 0, c2 = 0, c3 = 0;
        if (base + 3 < NN) {
            int4 v = *(const int4*)&g_cnt[base];
            c0 = v.x; c1 = v.y; c2 = v.z; c3 = v.w;
        } else {
            if (base < NN)     c0 = g_cnt[base];
            if (base + 1 < NN) c1 = g_cnt[base + 1];
            if (base + 2 < NN) c2 = g_cnt[base + 2];
            if (base + 3 < NN) c3 = g_cnt[base + 3];
        }
        int tsum = c0 + c1 + c2 + c3;
        int x = tsum;
#pragma unroll
        for (int off = 1; off < 32; off <<= 1) {
            int y = __shfl_up_sync(0xFFFFFFFFu, x, off);
            if (lane >= off) x += y;
        }
        if (lane == 31) wsum[w] = x;
        __syncthreads();
        if (w == 0) {
            int v = wsum[lane];
            int xx = v;
#pragma unroll
            for (int off = 1; off < 32; off <<= 1) {
                int y = __shfl_up_sync(0xFFFFFFFFu, xx, off);
                if (lane >= off) xx += y;
            }
            if (lane == 31) s_tot = xx;
            wsum[lane] = xx - v;  // exclusive warp offsets
        }
        __syncthreads();
        int excl = carry + wsum[w] + (x - tsum);
        if (base < NN)     { g_ptr[base]     = excl;                g_dinv[base]     = rsqrtf((float)c0); g_cnt[base]     = 0; }
        if (base + 1 < NN) { g_ptr[base + 1] = excl + c0;           g_dinv[base + 1] = rsqrtf((float)c1); g_cnt[base + 1] = 0; }
        if (base + 2 < NN) { g_ptr[base + 2] = excl + c0 + c1;      g_dinv[base + 2] = rsqrtf((float)c2); g_cnt[base + 2] = 0; }
        if (base + 3 < NN) { g_ptr[base + 3] = excl + c0 + c1 + c2; g_dinv[base + 3] = rsqrtf((float)c3); g_cnt[base + 3] = 0; }
        carry += s_tot;
        __syncthreads();
    }
    if (tid == 0) g_ptr[NN] = carry;  // == NTOT
}

// ---------------- launch 4: fill CSR ----------------
__global__ void k_fill() {
    int i = blockIdx.x * blockDim.x + threadIdx.x;
    if (i < NE) {
        unsigned r = (unsigned)g_esrc[i];
        unsigned c = (unsigned)g_edst[i];
        if (r < NN && c < NN) {
            int pos = g_ptr[c] + atomicAdd(&g_cnt[c], 1);
            g_src[pos] = (int)r;
            g_w[pos] = g_dinv[r] * g_dinv[c];
        }
    } else if (i < NTOT) {
        int n = i - NE;
        int pos = g_ptr[n] + atomicAdd(&g_cnt[n], 1);
        g_src[pos] = n;
        float d = g_dinv[n];
        g_w[pos] = d * d;
    }
}

// ---------------- launch 5: h0 = fp16(x), hidden = temp[0]*x ----------------
__global__ void k_init_h(const float* __restrict__ x, const float* __restrict__ temp) {
    int i = blockIdx.x * blockDim.x + threadIdx.x;  // float4 index
    if (i < NN * NF / 4) {
        float t0 = temp[0];
        float4 v = ((const float4*)x)[i];
        __half2 p0 = __floats2half2_rn(v.x, v.y);
        __half2 p1 = __floats2half2_rn(v.z, v.w);
        float2 st;
        *(__half2*)&st.x = p0;
        *(__half2*)&st.y = p1;
        ((float2*)g_h0)[i] = st;
        float4 hv = make_float4(t0 * v.x, t0 * v.y, t0 * v.z, t0 * v.w);
        ((float4*)g_hidden)[i] = hv;
    }
}

// ---------------- launches 6..15: one hop (warp per node, fp16 rows) -------
__global__ void k_prop(const float* __restrict__ temp, int k) {
    const __half* __restrict__ hin = (k & 1) ? g_h1 : g_h0;
    __half* __restrict__ hout      = (k & 1) ? g_h0 : g_h1;
    int node = blockIdx.x * 8 + (threadIdx.x >> 5);
    if (node >= NN) return;
    int lane = threadIdx.x & 31;
    int beg = __ldg(&g_ptr[node]), end = __ldg(&g_ptr[node + 1]);
    float tk = __ldg(&temp[k + 1]);

    float a0 = 0.f, a1 = 0.f, a2 = 0.f, a3 = 0.f;
    int e = beg;
    for (; e + 3 < end; e += 4) {
        int s0 = __ldg(&g_src[e]),     s1 = __ldg(&g_src[e + 1]);
        int s2 = __ldg(&g_src[e + 2]), s3 = __ldg(&g_src[e + 3]);
        float w0 = __ldg(&g_w[e]),     w1 = __ldg(&g_w[e + 1]);
        float w2 = __ldg(&g_w[e + 2]), w3 = __ldg(&g_w[e + 3]);
        float2 r0 = __ldg(&((const float2*)(hin + (size_t)s0 * NF))[lane]);
        float2 r1 = __ldg(&((const float2*)(hin + (size_t)s1 * NF))[lane]);
        float2 r2 = __ldg(&((const float2*)(hin + (size_t)s2 * NF))[lane]);
        float2 r3 = __ldg(&((const float2*)(hin + (size_t)s3 * NF))[lane]);
        {
            float2 fa = __half22float2(*(__half2*)&r0.x);
            float2 fb = __half22float2(*(__half2*)&r0.y);
            a0 += w0 * fa.x; a1 += w0 * fa.y; a2 += w0 * fb.x; a3 += w0 * fb.y;
        }
        {
            float2 fa = __half22float2(*(__half2*)&r1.x);
            float2 fb = __half22float2(*(__half2*)&r1.y);
            a0 += w1 * fa.x; a1 += w1 * fa.y; a2 += w1 * fb.x; a3 += w1 * fb.y;
        }
        {
            float2 fa = __half22float2(*(__half2*)&r2.x);
            float2 fb = __half22float2(*(__half2*)&r2.y);
            a0 += w2 * fa.x; a1 += w2 * fa.y; a2 += w2 * fb.x; a3 += w2 * fb.y;
        }
        {
            float2 fa = __half22float2(*(__half2*)&r3.x);
            float2 fb = __half22float2(*(__half2*)&r3.y);
            a0 += w3 * fa.x; a1 += w3 * fa.y; a2 += w3 * fb.x; a3 += w3 * fb.y;
        }
    }
    for (; e < end; e++) {
        int s = __ldg(&g_src[e]);
        float w = __ldg(&g_w[e]);
        float2 r = __ldg(&((const float2*)(hin + (size_t)s * NF))[lane]);
        float2 fa = __half22float2(*(__half2*)&r.x);
        float2 fb = __half22float2(*(__half2*)&r.y);
        a0 += w * fa.x; a1 += w * fa.y; a2 += w * fb.x; a3 += w * fb.y;
    }

    // store h_{k+1} as fp16
    {
        __half2 p0 = __floats2half2_rn(a0, a1);
        __half2 p1 = __floats2half2_rn(a2, a3);
        float2 st;
        *(__half2*)&st.x = p0;
        *(__half2*)&st.y = p1;
        ((float2*)(hout + (size_t)node * NF))[lane] = st;
    }
    // hidden += temp[k+1] * h_{k+1}  (fp32)
    {
        float4* hid = (float4*)(g_hidden + (size_t)node * NF);
        float4 hv = hid[lane];
        hv.x += tk * a0; hv.y += tk * a1; hv.z += tk * a2; hv.w += tk * a3;
        hid[lane] = hv;
    }
}

// ---------------- MLP layer 1: z1 = relu(hidden @ W1 + b1) ----------------
__global__ void k_mlp1(const float* __restrict__ B, const float* __restrict__ bias) {
    __shared__ float As[64][33];
    __shared__ float Bs[32][64];
    const float* __restrict__ A = g_hidden;
    float* __restrict__ C = g_z1;

    int tid = threadIdx.x;
    int brow = blockIdx.x * 64;
    int bcol = blockIdx.y * 64;
    int tr = (tid / 16) * 4;
    int tc = (tid % 16) * 4;

    float acc[4][4];
#pragma unroll
    for (int i = 0; i < 4; i++)
#pragma unroll
        for (int j = 0; j < 4; j++) acc[i][j] = 0.f;

    for (int k0 = 0; k0 < NF; k0 += 32) {
#pragma unroll
        for (int t = 0; t < 2; t++) {
            int i = tid + t * 256;
            int r = i / 8, c = (i % 8) * 4;
            float4 v;
            if (brow + r < NN)
                v = *(const float4*)&A[(size_t)(brow + r) * NF + k0 + c];
            else
                v = make_float4(0.f, 0.f, 0.f, 0.f);
            As[r][c] = v.x; As[r][c + 1] = v.y; As[r][c + 2] = v.z; As[r][c + 3] = v.w;
        }
#pragma unroll
        for (int t = 0; t < 2; t++) {
            int i = tid + t * 256;
            int r = i / 16, c = (i % 16) * 4;
            float4 v = *(const float4*)&B[(size_t)(k0 + r) * NH + bcol + c];
            *(float4*)&Bs[r][c] = v;
        }
        __syncthreads();
#pragma unroll
        for (int kk = 0; kk < 32; kk++) {
            float a[4];
#pragma unroll
            for (int i = 0; i < 4; i++) a[i] = As[tr + i][kk];
            float4 b = *(const float4*)&Bs[kk][tc];
#pragma unroll
            for (int i = 0; i < 4; i++) {
                acc[i][0] += a[i] * b.x;
                acc[i][1] += a[i] * b.y;
                acc[i][2] += a[i] * b.z;
                acc[i][3] += a[i] * b.w;
            }
        }
        __syncthreads();
    }

    float4 bb = *(const float4*)&bias[bcol + tc];
#pragma unroll
    for (int i = 0; i < 4; i++) {
        int r = brow + tr + i;
        if (r < NN) {
            float4 v;
            v.x = fmaxf(acc[i][0] + bb.x, 0.f);
            v.y = fmaxf(acc[i][1] + bb.y, 0.f);
            v.z = fmaxf(acc[i][2] + bb.z, 0.f);
            v.w = fmaxf(acc[i][3] + bb.w, 0.f);
            *(float4*)&C[(size_t)r * NH + bcol + tc] = v;
        }
    }
}

// ---------------- MLP layer 2 + log_softmax: thread per node --------------
__global__ void k_mlp2(const float* __restrict__ W2, const float* __restrict__ b2,
                       float* __restrict__ out) {
    __shared__ float Ws[NH * NC];
    __shared__ float bs[NC];
    for (int i = threadIdx.x; i < NH * NC; i += blockDim.x) Ws[i] = W2[i];
    if (threadIdx.x < NC) bs[threadIdx.x] = b2[threadIdx.x];
    __syncthreads();

    int node = blockIdx.x * blockDim.x + threadIdx.x;
    if (node >= NN) return;

    float acc[NC];
#pragma unroll
    for (int j = 0; j < NC; j++) acc[j] = bs[j];

    const float4* z4 = (const float4*)(g_z1 + (size_t)node * NH);
    for (int kk = 0; kk < NH / 4; kk++) {
        float4 z = z4[kk];
        int base = (kk * 4) * NC;
#pragma unroll
        for (int j = 0; j < NC; j++) {
            acc[j] += z.x * Ws[base + j] + z.y * Ws[base + NC + j]
                    + z.z * Ws[base + 2 * NC + j] + z.w * Ws[base + 3 * NC + j];
        }
    }

    float m = -1e30f;
#pragma unroll
    for (int j = 0; j < NC; j++) m = fmaxf(m, acc[j]);
    float s = 0.f;
#pragma unroll
    for (int j = 0; j < NC; j++) s += expf(acc[j] - m);
    float ls = logf(s);
    float* o = out + (size_t)node * NC;
#pragma unroll
    for (int j = 0; j < NC; j++) o[j] = acc[j] - m - ls;
}

// ---------------- launch ----------------
extern "C" void kernel_launch(void* const* d_in, const int* in_sizes, int n_in,
                              void* d_out, int out_size) {
    const float* x    = (const float*)d_in[0];
    const void*  ei   = d_in[1];
    const float* temp = (const float*)d_in[2];
    const float* W1   = (const float*)d_in[3];
    const float* b1   = (const float*)d_in[4];
    const float* W2   = (const float*)d_in[5];
    const float* b2   = (const float*)d_in[6];
    float*       out  = (float*)d_out;

    const int TB = 256;

    k_pre<<<(NN + TB - 1) / TB, TB>>>(ei);                    // 1
    k_convert<<<(NE + TB - 1) / TB, TB>>>(ei);                // 2
    k_scan<<<1, 1024>>>();                                    // 3
    k_fill<<<(NTOT + TB - 1) / TB, TB>>>();                   // 4
    k_init_h<<<(NN * NF / 4 + TB - 1) / TB, TB>>>(x, temp);   // 5

    for (int k = 0; k < KHOPS; k++) {                         // 6..15
        k_prop<<<(NN + 7) / 8, 256>>>(temp, k);
    }

    dim3 g1((NN + 63) / 64, NH / 64);
    k_mlp1<<<g1, 256>>>(W1, b1);                              // 16
    k_mlp2<<<(NN + 127) / 128, 128>>>(W2, b2, out);           // 17
}